// round 7
// baseline (speedup 1.0000x reference)
#include <cuda_runtime.h>
#include <cuda_bf16.h>
#include <math.h>

#define NFEAT   256
#define NHID    64
#define NCLASS  16
#define MAXN    50000

typedef unsigned long long ull;

// Scratch (allocation-free device globals). 16B-aligned for float4 / red.v4.
__device__ __align__(16) float g_S1[MAXN * NHID];    // x @ W1
__device__ __align__(16) float g_H [MAXN * NHID];    // spmm1 + b1 accum
__device__ __align__(16) float g_S2[MAXN * NCLASS];  // relu(H) @ W2
__device__ __align__(16) float g_O [MAXN * NCLASS];  // spmm2 + b2 accum

// ---------------------------------------------------------------------------
// f32x2 packed-FMA helpers (sm_100+ PTX; ptxas never auto-fuses these)
// ---------------------------------------------------------------------------
__device__ __forceinline__ ull fma2(ull a, ull b, ull c) {
    ull d;
    asm("fma.rn.f32x2 %0, %1, %2, %3;" : "=l"(d) : "l"(a), "l"(b), "l"(c));
    return d;
}
__device__ __forceinline__ ull pack2(float x) {
    ull d; unsigned int u = __float_as_uint(x);
    asm("mov.b64 %0, {%1, %2};" : "=l"(d) : "r"(u), "r"(u));
    return d;
}

// ---------------------------------------------------------------------------
// GEMM1: S1[N,64] = x[N,256] @ W1[256,64]
// 64x64 tile, 256 threads, 2 rows x 8 cols per thread, FFMA2 inner.
// ---------------------------------------------------------------------------
__global__ void __launch_bounds__(256) gemm1_kernel(
    const float* __restrict__ x, const float* __restrict__ W1, int n_nodes)
{
    __shared__ float xs[64][33];
    __shared__ float ws[32][64];

    const int tid = threadIdx.x;
    const int tx = tid & 7;          // 8 cols at 8*tx
    const int ty = tid >> 3;         // rows {ty, ty+32}
    const int rowBase = blockIdx.x * 64;

    ull acc0[4], acc1[4];
#pragma unroll
    for (int p = 0; p < 4; p++) { acc0[p] = 0ull; acc1[p] = 0ull; }

#pragma unroll 1
    for (int k0 = 0; k0 < NFEAT; k0 += 32) {
#pragma unroll
        for (int j = 0; j < 2; j++) {
            int s = tid * 2 + j;               // 0..511
            int r = s >> 3;                    // 0..63
            int c4 = s & 7;                    // 0..7
            float4 v = make_float4(0.f, 0.f, 0.f, 0.f);
            int grow = rowBase + r;
            if (grow < n_nodes)
                v = *reinterpret_cast<const float4*>(&x[grow * NFEAT + k0 + c4 * 4]);
            xs[r][c4 * 4 + 0] = v.x; xs[r][c4 * 4 + 1] = v.y;
            xs[r][c4 * 4 + 2] = v.z; xs[r][c4 * 4 + 3] = v.w;
        }
#pragma unroll
        for (int j = 0; j < 2; j++) {
            int s = tid * 2 + j;
            int kk = s >> 4;
            int c4 = s & 15;
            float4 v = *reinterpret_cast<const float4*>(&W1[(k0 + kk) * NHID + c4 * 4]);
            *reinterpret_cast<float4*>(&ws[kk][c4 * 4]) = v;
        }
        __syncthreads();

#pragma unroll
        for (int kk = 0; kk < 32; kk++) {
            ull a0 = pack2(xs[ty][kk]);
            ull a1 = pack2(xs[ty + 32][kk]);
            ulonglong2 w01 = *reinterpret_cast<const ulonglong2*>(&ws[kk][8 * tx]);
            ulonglong2 w23 = *reinterpret_cast<const ulonglong2*>(&ws[kk][8 * tx + 4]);
            acc0[0] = fma2(a0, w01.x, acc0[0]);
            acc0[1] = fma2(a0, w01.y, acc0[1]);
            acc0[2] = fma2(a0, w23.x, acc0[2]);
            acc0[3] = fma2(a0, w23.y, acc0[3]);
            acc1[0] = fma2(a1, w01.x, acc1[0]);
            acc1[1] = fma2(a1, w01.y, acc1[1]);
            acc1[2] = fma2(a1, w23.x, acc1[2]);
            acc1[3] = fma2(a1, w23.y, acc1[3]);
        }
        __syncthreads();
    }

    int r0 = rowBase + ty, r1 = rowBase + ty + 32;
    if (r0 < n_nodes) {
#pragma unroll
        for (int p = 0; p < 4; p++)
            *reinterpret_cast<ull*>(&g_S1[r0 * NHID + 8 * tx + 2 * p]) = acc0[p];
    }
    if (r1 < n_nodes) {
#pragma unroll
        for (int p = 0; p < 4; p++)
            *reinterpret_cast<ull*>(&g_S1[r1 * NHID + 8 * tx + 2 * p]) = acc1[p];
    }
}

// ---------------------------------------------------------------------------
// Init H with b1 broadcast (vectorized): H row-major, 16 float4 per row
// ---------------------------------------------------------------------------
__global__ void init_h_kernel(const float* __restrict__ b1, int n_nodes)
{
    int idx = blockIdx.x * blockDim.x + threadIdx.x;   // float4 index
    int total = n_nodes * (NHID / 4);
    if (idx < total) {
        int c4 = idx & (NHID / 4 - 1);
        float4 v = *reinterpret_cast<const float4*>(&b1[c4 * 4]);
        *reinterpret_cast<float4*>(&g_H[idx * 4]) = v;
    }
}

// ---------------------------------------------------------------------------
// SpMM1 (push): H[dst] += w * S1[src]  (16 threads/edge, red.v4 each)
// ---------------------------------------------------------------------------
__global__ void __launch_bounds__(256) spmm1_kernel(
    const int* __restrict__ src, const int* __restrict__ dst,
    const float* __restrict__ ew, int n_edges)
{
    long long t = (long long)blockIdx.x * blockDim.x + threadIdx.x;
    int e = (int)(t >> 4);
    if (e >= n_edges) return;
    int lane = (int)(t & 15);
    int s = src[e];
    int d = dst[e];
    float w = ew[e];
    float4 v = *reinterpret_cast<const float4*>(&g_S1[s * NHID + lane * 4]);
    float mx = v.x * w, my = v.y * w, mz = v.z * w, mw = v.w * w;
    float* p = &g_H[d * NHID + lane * 4];
    asm volatile("red.global.add.v4.f32 [%0], {%1, %2, %3, %4};"
                 :: "l"(p), "f"(mx), "f"(my), "f"(mz), "f"(mw) : "memory");
}

// ---------------------------------------------------------------------------
// GEMM2 fused ReLU: S2[N,16] = relu(H)[N,64] @ W2[64,16]
// 128x16 tile, 256 threads, 2 rows x 4 cols per thread, FFMA2 inner.
// ---------------------------------------------------------------------------
__global__ void __launch_bounds__(256) gemm2_kernel(
    const float* __restrict__ W2, int n_nodes)
{
    __shared__ float hs[128][68];
    __shared__ float ws2[64][16];

    const int tid = threadIdx.x;
    const int tx = tid & 3;          // 4 cols at 4*tx
    const int ty = tid >> 2;         // rows {ty, ty+64}
    const int rowBase = blockIdx.x * 128;

#pragma unroll
    for (int j = 0; j < 8; j++) {
        int s = tid + j * 256;
        int r = s >> 4;
        int c4 = s & 15;
        float4 v = make_float4(0.f, 0.f, 0.f, 0.f);
        int grow = rowBase + r;
        if (grow < n_nodes)
            v = *reinterpret_cast<const float4*>(&g_H[grow * NHID + c4 * 4]);
        v.x = fmaxf(v.x, 0.f); v.y = fmaxf(v.y, 0.f);
        v.z = fmaxf(v.z, 0.f); v.w = fmaxf(v.w, 0.f);
        *reinterpret_cast<float4*>(&hs[r][c4 * 4]) = v;
    }
    {
        int kk = tid >> 2;
        int c4 = tid & 3;
        float4 v = *reinterpret_cast<const float4*>(&W2[kk * NCLASS + c4 * 4]);
        *reinterpret_cast<float4*>(&ws2[kk][c4 * 4]) = v;
    }
    __syncthreads();

    ull acc0[2] = {0ull, 0ull};
    ull acc1[2] = {0ull, 0ull};
#pragma unroll
    for (int kk = 0; kk < NHID; kk++) {
        ull a0 = pack2(hs[ty][kk]);
        ull a1 = pack2(hs[ty + 64][kk]);
        ulonglong2 w = *reinterpret_cast<const ulonglong2*>(&ws2[kk][4 * tx]);
        acc0[0] = fma2(a0, w.x, acc0[0]);
        acc0[1] = fma2(a0, w.y, acc0[1]);
        acc1[0] = fma2(a1, w.x, acc1[0]);
        acc1[1] = fma2(a1, w.y, acc1[1]);
    }

    int r0 = rowBase + ty, r1 = rowBase + ty + 64;
    if (r0 < n_nodes) {
        *reinterpret_cast<ull*>(&g_S2[r0 * NCLASS + 4 * tx])     = acc0[0];
        *reinterpret_cast<ull*>(&g_S2[r0 * NCLASS + 4 * tx + 2]) = acc0[1];
    }
    if (r1 < n_nodes) {
        *reinterpret_cast<ull*>(&g_S2[r1 * NCLASS + 4 * tx])     = acc1[0];
        *reinterpret_cast<ull*>(&g_S2[r1 * NCLASS + 4 * tx + 2]) = acc1[1];
    }
}

// ---------------------------------------------------------------------------
// Init O with b2 broadcast (vectorized)
// ---------------------------------------------------------------------------
__global__ void init_o_kernel(const float* __restrict__ b2, int n_nodes)
{
    int idx = blockIdx.x * blockDim.x + threadIdx.x;   // float4 index
    int total = n_nodes * (NCLASS / 4);
    if (idx < total) {
        int c4 = idx & (NCLASS / 4 - 1);
        float4 v = *reinterpret_cast<const float4*>(&b2[c4 * 4]);
        *reinterpret_cast<float4*>(&g_O[idx * 4]) = v;
    }
}

// ---------------------------------------------------------------------------
// SpMM2 (push): O[dst] += w * S2[src]  (4 threads/edge, red.v4 each)
// ---------------------------------------------------------------------------
__global__ void __launch_bounds__(256) spmm2_kernel(
    const int* __restrict__ src, const int* __restrict__ dst,
    const float* __restrict__ ew, int n_edges)
{
    long long t = (long long)blockIdx.x * blockDim.x + threadIdx.x;
    int e = (int)(t >> 2);
    if (e >= n_edges) return;
    int q = (int)(t & 3);
    int s = src[e];
    int d = dst[e];
    float w = ew[e];
    float4 v = *reinterpret_cast<const float4*>(&g_S2[s * NCLASS + q * 4]);
    float mx = v.x * w, my = v.y * w, mz = v.z * w, mw = v.w * w;
    float* p = &g_O[d * NCLASS + q * 4];
    asm volatile("red.global.add.v4.f32 [%0], {%1, %2, %3, %4};"
                 :: "l"(p), "f"(mx), "f"(my), "f"(mz), "f"(mw) : "memory");
}

// ---------------------------------------------------------------------------
// log_softmax over 16 classes, one thread per row
// ---------------------------------------------------------------------------
__global__ void logsoftmax_kernel(float* __restrict__ out, int n_nodes)
{
    int i = blockIdx.x * blockDim.x + threadIdx.x;
    if (i >= n_nodes) return;
    float v[NCLASS];
#pragma unroll
    for (int j = 0; j < 4; j++) {
        float4 t = *reinterpret_cast<const float4*>(&g_O[i * NCLASS + j * 4]);
        v[j * 4 + 0] = t.x; v[j * 4 + 1] = t.y; v[j * 4 + 2] = t.z; v[j * 4 + 3] = t.w;
    }
    float m = v[0];
#pragma unroll
    for (int j = 1; j < NCLASS; j++) m = fmaxf(m, v[j]);
    float sum = 0.f;
#pragma unroll
    for (int j = 0; j < NCLASS; j++) sum += expf(v[j] - m);
    float lse = logf(sum);
#pragma unroll
    for (int j = 0; j < 4; j++) {
        float4 t = make_float4(v[j * 4 + 0] - m - lse, v[j * 4 + 1] - m - lse,
                               v[j * 4 + 2] - m - lse, v[j * 4 + 3] - m - lse);
        *reinterpret_cast<float4*>(&out[i * NCLASS + j * 4]) = t;
    }
}

// ---------------------------------------------------------------------------
// Launch.  Inputs: x, W1, b1, W2, b2, edge_src, edge_dst, edge_weight
// ---------------------------------------------------------------------------
extern "C" void kernel_launch(void* const* d_in, const int* in_sizes, int n_in,
                              void* d_out, int out_size)
{
    const float* x    = (const float*)d_in[0];
    const float* W1   = (const float*)d_in[1];
    const float* b1   = (const float*)d_in[2];
    const float* W2   = (const float*)d_in[3];
    const float* b2   = (const float*)d_in[4];
    const int*   esrc = (const int*)d_in[5];
    const int*   edst = (const int*)d_in[6];
    const float* ew   = (const float*)d_in[7];

    int n_nodes = in_sizes[0] / NFEAT;
    int n_edges = in_sizes[5];

    // Layer 1
    init_h_kernel<<<(n_nodes * (NHID / 4) + 255) / 256, 256>>>(b1, n_nodes);
    gemm1_kernel<<<(n_nodes + 63) / 64, 256>>>(x, W1, n_nodes);
    {
        long long threads = (long long)n_edges * 16;
        int blocks = (int)((threads + 255) / 256);
        spmm1_kernel<<<blocks, 256>>>(esrc, edst, ew, n_edges);
    }

    // Layer 2
    init_o_kernel<<<(n_nodes * (NCLASS / 4) + 255) / 256, 256>>>(b2, n_nodes);
    gemm2_kernel<<<(n_nodes + 127) / 128, 256>>>(W2, n_nodes);
    {
        long long threads = (long long)n_edges * 4;
        int blocks = (int)((threads + 255) / 256);
        spmm2_kernel<<<blocks, 256>>>(esrc, edst, ew, n_edges);
    }

    // Output
    logsoftmax_kernel<<<(n_nodes + 255) / 256, 256>>>((float*)d_out, n_nodes);
}

// round 8
// speedup vs baseline: 1.5483x; 1.5483x over previous
#include <cuda_runtime.h>
#include <cuda_bf16.h>
#include <math.h>

#define NFEAT   256
#define NHID    64
#define NCLASS  16
#define MAXN    50000
#define MAXE    1600000

// ---------------------------------------------------------------------------
// Scratch (allocation-free device globals)
// ---------------------------------------------------------------------------
__device__ __align__(16) float g_S1[MAXN * NHID];     // x @ W1
__device__ __align__(16) float g_H [MAXN * NHID];     // spmm1 + b1
__device__ __align__(16) float g_S2[MAXN * NCLASS];   // relu(H) @ W2

__device__ int  g_cnt[MAXN];          // in-degree per dst
__device__ int  g_off[MAXN];          // CSR row offsets
__device__ int  g_cur[MAXN];          // scatter cursors
__device__ int  g_blksum[256];        // scan partials
__device__ __align__(8) int2 g_csr[MAXE];   // packed (src, w-bits), by dst

// ---------------------------------------------------------------------------
// GEMM1: S1[N,64] = x[N,256] @ W1[256,64]
// 64x64 tile, 256 threads, 4x4 register blocking, plain FFMA (R3-proven).
// ---------------------------------------------------------------------------
__global__ void __launch_bounds__(256) gemm1_kernel(
    const float* __restrict__ x, const float* __restrict__ W1, int n_nodes)
{
    __shared__ float xs[64][33];
    __shared__ float ws[32][64];

    const int tid = threadIdx.x;
    const int tx = tid & 15;        // cols 4*tx .. 4*tx+3
    const int ty = tid >> 4;        // rows 4*ty .. 4*ty+3
    const int rowBase = blockIdx.x * 64;

    float acc[4][4];
#pragma unroll
    for (int i = 0; i < 4; i++)
#pragma unroll
        for (int j = 0; j < 4; j++) acc[i][j] = 0.f;

#pragma unroll 1
    for (int k0 = 0; k0 < NFEAT; k0 += 32) {
#pragma unroll
        for (int j = 0; j < 2; j++) {
            int s = tid * 2 + j;          // 0..511
            int r = s >> 3;               // 0..63
            int c4 = s & 7;               // 0..7
            float4 v = make_float4(0.f, 0.f, 0.f, 0.f);
            int grow = rowBase + r;
            if (grow < n_nodes)
                v = *reinterpret_cast<const float4*>(&x[grow * NFEAT + k0 + c4 * 4]);
            xs[r][c4 * 4 + 0] = v.x; xs[r][c4 * 4 + 1] = v.y;
            xs[r][c4 * 4 + 2] = v.z; xs[r][c4 * 4 + 3] = v.w;
        }
#pragma unroll
        for (int j = 0; j < 2; j++) {
            int s = tid * 2 + j;
            int kk = s >> 4;
            int c4 = s & 15;
            float4 v = *reinterpret_cast<const float4*>(&W1[(k0 + kk) * NHID + c4 * 4]);
            *reinterpret_cast<float4*>(&ws[kk][c4 * 4]) = v;
        }
        __syncthreads();

#pragma unroll
        for (int kk = 0; kk < 32; kk++) {
            float4 w = *reinterpret_cast<const float4*>(&ws[kk][4 * tx]);
            float a0 = xs[4 * ty + 0][kk];
            float a1 = xs[4 * ty + 1][kk];
            float a2 = xs[4 * ty + 2][kk];
            float a3 = xs[4 * ty + 3][kk];
            acc[0][0] += a0 * w.x; acc[0][1] += a0 * w.y; acc[0][2] += a0 * w.z; acc[0][3] += a0 * w.w;
            acc[1][0] += a1 * w.x; acc[1][1] += a1 * w.y; acc[1][2] += a1 * w.z; acc[1][3] += a1 * w.w;
            acc[2][0] += a2 * w.x; acc[2][1] += a2 * w.y; acc[2][2] += a2 * w.z; acc[2][3] += a2 * w.w;
            acc[3][0] += a3 * w.x; acc[3][1] += a3 * w.y; acc[3][2] += a3 * w.z; acc[3][3] += a3 * w.w;
        }
        __syncthreads();
    }

#pragma unroll
    for (int i = 0; i < 4; i++) {
        int grow = rowBase + 4 * ty + i;
        if (grow < n_nodes) {
            float4 v = make_float4(acc[i][0], acc[i][1], acc[i][2], acc[i][3]);
            *reinterpret_cast<float4*>(&g_S1[grow * NHID + 4 * tx]) = v;
        }
    }
}

// ---------------------------------------------------------------------------
// CSR build: zero -> histogram -> scan (3 stages) -> scatter (packed int2)
// ---------------------------------------------------------------------------
__global__ void zero_cnt_kernel(int n)
{
    int i = blockIdx.x * blockDim.x + threadIdx.x;
    if (i < n) g_cnt[i] = 0;
}

__global__ void hist_kernel(const int* __restrict__ dst, int n_edges)
{
    int e = blockIdx.x * blockDim.x + threadIdx.x;
    if (e < n_edges) atomicAdd(&g_cnt[dst[e]], 1);
}

__global__ void __launch_bounds__(512) scan_part_kernel(int n)
{
    __shared__ int wsum[16];
    int i = blockIdx.x * 512 + threadIdx.x;
    int lane = threadIdx.x & 31, wid = threadIdx.x >> 5;
    int v = (i < n) ? g_cnt[i] : 0;
    int x = v;
#pragma unroll
    for (int o = 1; o < 32; o <<= 1) {
        int t = __shfl_up_sync(0xffffffffu, x, o);
        if (lane >= o) x += t;
    }
    if (lane == 31) wsum[wid] = x;
    __syncthreads();
    if (wid == 0) {
        int s = (lane < 16) ? wsum[lane] : 0;
#pragma unroll
        for (int o = 1; o < 16; o <<= 1) {
            int t = __shfl_up_sync(0xffffffffu, s, o);
            if (lane >= o) s += t;
        }
        if (lane < 16) wsum[lane] = s;
    }
    __syncthreads();
    int base = (wid > 0) ? wsum[wid - 1] : 0;
    int excl = base + x - v;
    if (i < n) g_off[i] = excl;
    if (threadIdx.x == 511) g_blksum[blockIdx.x] = base + x;
}

// Parallel scan of up to 256 block partials (1 block of 256 threads)
__global__ void __launch_bounds__(256) scan_block_kernel(int nb)
{
    __shared__ int wsum[8];
    int t = threadIdx.x;
    int lane = t & 31, wid = t >> 5;
    int v = (t < nb) ? g_blksum[t] : 0;
    int x = v;
#pragma unroll
    for (int o = 1; o < 32; o <<= 1) {
        int s = __shfl_up_sync(0xffffffffu, x, o);
        if (lane >= o) x += s;
    }
    if (lane == 31) wsum[wid] = x;
    __syncthreads();
    if (wid == 0 && lane < 8) {
        int s = wsum[lane];
#pragma unroll
        for (int o = 1; o < 8; o <<= 1) {
            int u = __shfl_up_sync(0x000000ffu, s, o);
            if (lane >= o) s += u;
        }
        wsum[lane] = s;
    }
    __syncthreads();
    int base = (wid > 0) ? wsum[wid - 1] : 0;
    if (t < nb) g_blksum[t] = base + x - v;   // exclusive
}

__global__ void scan_add_kernel(int n)
{
    int i = blockIdx.x * blockDim.x + threadIdx.x;
    if (i < n) {
        int o = g_off[i] + g_blksum[i >> 9];
        g_off[i] = o;
        g_cur[i] = o;
    }
}

__global__ void scatter_kernel(
    const int* __restrict__ src, const int* __restrict__ dst,
    const float* __restrict__ ew, int n_edges)
{
    int e = blockIdx.x * blockDim.x + threadIdx.x;
    if (e < n_edges) {
        int d = dst[e];
        int p = atomicAdd(&g_cur[d], 1);
        g_csr[p] = make_int2(src[e], __float_as_int(ew[e]));
    }
}

// ---------------------------------------------------------------------------
// SpMM1 (pull): H[d] = b1 + sum_e w_e * S1[src_e]   — warp per dst, no atomics
// Lane owns 2 features (float2). Unroll x4 for gather MLP.
// ---------------------------------------------------------------------------
__global__ void __launch_bounds__(256) spmm1_pull_kernel(
    const float* __restrict__ b1, int n_nodes)
{
    int lane = threadIdx.x & 31;
    int d = blockIdx.x * 8 + (threadIdx.x >> 5);
    if (d >= n_nodes) return;

    float2 acc = *reinterpret_cast<const float2*>(&b1[2 * lane]);
    int beg = g_off[d];
    int end = beg + g_cnt[d];

    int j = beg;
    for (; j + 3 < end; j += 4) {
        int2 e0 = g_csr[j + 0];
        int2 e1 = g_csr[j + 1];
        int2 e2 = g_csr[j + 2];
        int2 e3 = g_csr[j + 3];
        float2 v0 = *reinterpret_cast<const float2*>(&g_S1[e0.x * NHID + 2 * lane]);
        float2 v1 = *reinterpret_cast<const float2*>(&g_S1[e1.x * NHID + 2 * lane]);
        float2 v2 = *reinterpret_cast<const float2*>(&g_S1[e2.x * NHID + 2 * lane]);
        float2 v3 = *reinterpret_cast<const float2*>(&g_S1[e3.x * NHID + 2 * lane]);
        float w0 = __int_as_float(e0.y), w1 = __int_as_float(e1.y);
        float w2 = __int_as_float(e2.y), w3 = __int_as_float(e3.y);
        acc.x = fmaf(w0, v0.x, acc.x); acc.y = fmaf(w0, v0.y, acc.y);
        acc.x = fmaf(w1, v1.x, acc.x); acc.y = fmaf(w1, v1.y, acc.y);
        acc.x = fmaf(w2, v2.x, acc.x); acc.y = fmaf(w2, v2.y, acc.y);
        acc.x = fmaf(w3, v3.x, acc.x); acc.y = fmaf(w3, v3.y, acc.y);
    }
    for (; j < end; j++) {
        int2 e = g_csr[j];
        float2 v = *reinterpret_cast<const float2*>(&g_S1[e.x * NHID + 2 * lane]);
        float w = __int_as_float(e.y);
        acc.x = fmaf(w, v.x, acc.x); acc.y = fmaf(w, v.y, acc.y);
    }
    *reinterpret_cast<float2*>(&g_H[d * NHID + 2 * lane]) = acc;
}

// ---------------------------------------------------------------------------
// GEMM2 fused ReLU: S2[N,16] = relu(H)[N,64] @ W2[64,16]
// 128x16 tile, 256 threads, 2 rows x 4 cols per thread, plain FFMA.
// ---------------------------------------------------------------------------
__global__ void __launch_bounds__(256) gemm2_kernel(
    const float* __restrict__ W2, int n_nodes)
{
    __shared__ float hs[128][68];
    __shared__ float ws2[64][16];

    const int tid = threadIdx.x;
    const int tx = tid & 3;          // cols 4*tx .. 4*tx+3
    const int ty = tid >> 2;         // rows {ty, ty+64}
    const int rowBase = blockIdx.x * 128;

#pragma unroll
    for (int j = 0; j < 8; j++) {
        int s = tid + j * 256;
        int r = s >> 4;
        int c4 = s & 15;
        float4 v = make_float4(0.f, 0.f, 0.f, 0.f);
        int grow = rowBase + r;
        if (grow < n_nodes)
            v = *reinterpret_cast<const float4*>(&g_H[grow * NHID + c4 * 4]);
        v.x = fmaxf(v.x, 0.f); v.y = fmaxf(v.y, 0.f);
        v.z = fmaxf(v.z, 0.f); v.w = fmaxf(v.w, 0.f);
        *reinterpret_cast<float4*>(&hs[r][c4 * 4]) = v;
    }
    {
        int kk = tid >> 2;
        int c4 = tid & 3;
        float4 v = *reinterpret_cast<const float4*>(&W2[kk * NCLASS + c4 * 4]);
        *reinterpret_cast<float4*>(&ws2[kk][c4 * 4]) = v;
    }
    __syncthreads();

    float acc0[4] = {0.f, 0.f, 0.f, 0.f};
    float acc1[4] = {0.f, 0.f, 0.f, 0.f};
#pragma unroll
    for (int kk = 0; kk < NHID; kk++) {
        float a0 = hs[ty][kk];
        float a1 = hs[ty + 64][kk];
        float4 w = *reinterpret_cast<const float4*>(&ws2[kk][4 * tx]);
        acc0[0] = fmaf(a0, w.x, acc0[0]); acc0[1] = fmaf(a0, w.y, acc0[1]);
        acc0[2] = fmaf(a0, w.z, acc0[2]); acc0[3] = fmaf(a0, w.w, acc0[3]);
        acc1[0] = fmaf(a1, w.x, acc1[0]); acc1[1] = fmaf(a1, w.y, acc1[1]);
        acc1[2] = fmaf(a1, w.z, acc1[2]); acc1[3] = fmaf(a1, w.w, acc1[3]);
    }

    int r0 = rowBase + ty, r1 = rowBase + ty + 64;
    if (r0 < n_nodes)
        *reinterpret_cast<float4*>(&g_S2[r0 * NCLASS + 4 * tx]) =
            make_float4(acc0[0], acc0[1], acc0[2], acc0[3]);
    if (r1 < n_nodes)
        *reinterpret_cast<float4*>(&g_S2[r1 * NCLASS + 4 * tx]) =
            make_float4(acc1[0], acc1[1], acc1[2], acc1[3]);
}

// ---------------------------------------------------------------------------
// SpMM2 (pull) + bias + log_softmax fused: out[d] = lsm(b2 + sum w*S2[src])
// 16 lanes per dst (1 class each); shfl reductions within 16-group.
// ---------------------------------------------------------------------------
__global__ void __launch_bounds__(256) spmm2_lsm_kernel(
    const float* __restrict__ b2, float* __restrict__ out, int n_nodes)
{
    int lane16 = threadIdx.x & 15;
    int d = blockIdx.x * 16 + (threadIdx.x >> 4);
    if (d >= n_nodes) return;

    float acc = b2[lane16];
    int beg = g_off[d];
    int end = beg + g_cnt[d];

    int j = beg;
    for (; j + 1 < end; j += 2) {
        int2 e0 = g_csr[j];
        int2 e1 = g_csr[j + 1];
        float v0 = g_S2[e0.x * NCLASS + lane16];
        float v1 = g_S2[e1.x * NCLASS + lane16];
        acc = fmaf(__int_as_float(e0.y), v0, acc);
        acc = fmaf(__int_as_float(e1.y), v1, acc);
    }
    if (j < end) {
        int2 e = g_csr[j];
        acc = fmaf(__int_as_float(e.y), g_S2[e.x * NCLASS + lane16], acc);
    }

    float m = acc;
#pragma unroll
    for (int o = 8; o >= 1; o >>= 1)
        m = fmaxf(m, __shfl_xor_sync(0xffffffffu, m, o, 16));
    float ssum = expf(acc - m);
#pragma unroll
    for (int o = 8; o >= 1; o >>= 1)
        ssum += __shfl_xor_sync(0xffffffffu, ssum, o, 16);
    out[d * NCLASS + lane16] = acc - m - logf(ssum);
}

// ---------------------------------------------------------------------------
// Launch.  Inputs: x, W1, b1, W2, b2, edge_src, edge_dst, edge_weight
// ---------------------------------------------------------------------------
extern "C" void kernel_launch(void* const* d_in, const int* in_sizes, int n_in,
                              void* d_out, int out_size)
{
    const float* x    = (const float*)d_in[0];
    const float* W1   = (const float*)d_in[1];
    const float* b1   = (const float*)d_in[2];
    const float* W2   = (const float*)d_in[3];
    const float* b2   = (const float*)d_in[4];
    const int*   esrc = (const int*)d_in[5];
    const int*   edst = (const int*)d_in[6];
    const float* ew   = (const float*)d_in[7];

    int n_nodes = in_sizes[0] / NFEAT;
    int n_edges = in_sizes[5];
    int nb = (n_nodes + 511) / 512;

    // CSR-by-dst build (overlaps nothing, but cheap)
    zero_cnt_kernel<<<(n_nodes + 255) / 256, 256>>>(n_nodes);
    hist_kernel<<<(n_edges + 255) / 256, 256>>>(edst, n_edges);
    scan_part_kernel<<<nb, 512>>>(n_nodes);
    scan_block_kernel<<<1, 256>>>(nb);
    scan_add_kernel<<<(n_nodes + 255) / 256, 256>>>(n_nodes);
    scatter_kernel<<<(n_edges + 255) / 256, 256>>>(esrc, edst, ew, n_edges);

    // GEMM1
    gemm1_kernel<<<(n_nodes + 63) / 64, 256>>>(x, W1, n_nodes);

    // Layer 1 aggregate (pull, warp/dst, no atomics)
    spmm1_pull_kernel<<<(n_nodes + 7) / 8, 256>>>(b1, n_nodes);

    // Layer 2
    gemm2_kernel<<<(n_nodes + 127) / 128, 256>>>(W2, n_nodes);
    spmm2_lsm_kernel<<<(n_nodes + 15) / 16, 256>>>(b2, (float*)d_out, n_nodes);
}

// round 10
// speedup vs baseline: 1.9010x; 1.2278x over previous
#include <cuda_runtime.h>
#include <cuda_bf16.h>
#include <math.h>

#define NFEAT   256
#define NHID    64
#define NCLASS  16
#define MAXN    50000
#define MAXE    1600000

// ---------------------------------------------------------------------------
// Scratch (allocation-free device globals)
// ---------------------------------------------------------------------------
__device__ __align__(16) float g_S1[MAXN * NHID];     // x @ W1
__device__ __align__(16) float g_H [MAXN * NHID];     // spmm1 + b1
__device__ __align__(16) float g_S2[MAXN * NCLASS];   // relu(H) @ W2

__device__ int  g_cnt[MAXN];            // in-degree per dst
__device__ int  g_off[MAXN];            // CSR row offsets
__device__ int  g_cur[MAXN];            // scatter cursors
__device__ int  g_state[128];           // decoupled-lookback state: (sum<<2)|flag
__device__ __align__(16) int2 g_csr[MAXE];   // packed (src, w-bits), grouped by dst

// ---------------------------------------------------------------------------
// GEMM1 via tf32 tensor cores: S1[N,64] = x[N,256] @ W1[256,64]
// 64x64 tile / block (256 thr, 8 warps). Warp w -> m-tile (w>>1)*16, n-half (w&1)*32.
// mma.sync.aligned.m16n8k8.row.col.f32.tf32.tf32.f32, RNA-rounded inputs.
// ---------------------------------------------------------------------------
__device__ __forceinline__ unsigned f2tf32(float f) {
    unsigned u;
    asm("cvt.rna.tf32.f32 %0, %1;" : "=r"(u) : "f"(f));
    return u;
}

__global__ void __launch_bounds__(256) gemm1_tf32_kernel(
    const float* __restrict__ x, const float* __restrict__ W1, int n_nodes)
{
    __shared__ unsigned xs[64][36];   // pitch 36: A-frag LDS conflict-free
    __shared__ unsigned ws[32][72];   // pitch 72: B-frag LDS conflict-free

    const int tid = threadIdx.x;
    const int w   = tid >> 5;
    const int lane = tid & 31;
    const int mw = w >> 1;            // rows 16*mw .. +15
    const int nw = w & 1;             // cols 32*nw .. +31
    const int lr = lane >> 2;         // 0..7
    const int lc = lane & 3;          // 0..3
    const int rowBase = blockIdx.x * 64;

    float acc[4][4];                  // 4 n-subtiles x 4 frag regs
#pragma unroll
    for (int i = 0; i < 4; i++)
#pragma unroll
        for (int j = 0; j < 4; j++) acc[i][j] = 0.f;

#pragma unroll 1
    for (int k0 = 0; k0 < NFEAT; k0 += 32) {
        // x tile: 64 rows x 32 k = 512 float4; 2 per thread (cvt to tf32)
#pragma unroll
        for (int j = 0; j < 2; j++) {
            int s = tid * 2 + j;              // 0..511
            int r = s >> 3;                   // 0..63
            int c4 = s & 7;                   // 0..7
            float4 v = make_float4(0.f, 0.f, 0.f, 0.f);
            int grow = rowBase + r;
            if (grow < n_nodes)
                v = *reinterpret_cast<const float4*>(&x[grow * NFEAT + k0 + c4 * 4]);
            xs[r][c4 * 4 + 0] = f2tf32(v.x);
            xs[r][c4 * 4 + 1] = f2tf32(v.y);
            xs[r][c4 * 4 + 2] = f2tf32(v.z);
            xs[r][c4 * 4 + 3] = f2tf32(v.w);
        }
        // W1 tile: 32 k x 64 cols = 512 float4; 2 per thread
#pragma unroll
        for (int j = 0; j < 2; j++) {
            int s = tid * 2 + j;
            int kk = s >> 4;
            int c4 = s & 15;
            float4 v = *reinterpret_cast<const float4*>(&W1[(k0 + kk) * NHID + c4 * 4]);
            ws[kk][c4 * 4 + 0] = f2tf32(v.x);
            ws[kk][c4 * 4 + 1] = f2tf32(v.y);
            ws[kk][c4 * 4 + 2] = f2tf32(v.z);
            ws[kk][c4 * 4 + 3] = f2tf32(v.w);
        }
        __syncthreads();

#pragma unroll
        for (int k8 = 0; k8 < 32; k8 += 8) {
            // A fragment (m16 x k8, .row layout)
            unsigned a0 = xs[16 * mw + lr    ][k8 + lc    ];
            unsigned a1 = xs[16 * mw + lr + 8][k8 + lc    ];
            unsigned a2 = xs[16 * mw + lr    ][k8 + lc + 4];
            unsigned a3 = xs[16 * mw + lr + 8][k8 + lc + 4];
#pragma unroll
            for (int nt = 0; nt < 4; nt++) {
                int ncol = 32 * nw + 8 * nt + lr;
                unsigned b0 = ws[k8 + lc    ][ncol];
                unsigned b1 = ws[k8 + lc + 4][ncol];
                asm volatile(
                    "mma.sync.aligned.m16n8k8.row.col.f32.tf32.tf32.f32 "
                    "{%0,%1,%2,%3}, {%4,%5,%6,%7}, {%8,%9}, {%0,%1,%2,%3};"
                    : "+f"(acc[nt][0]), "+f"(acc[nt][1]),
                      "+f"(acc[nt][2]), "+f"(acc[nt][3])
                    : "r"(a0), "r"(a1), "r"(a2), "r"(a3), "r"(b0), "r"(b1));
            }
        }
        __syncthreads();
    }

    // Store: c0,c1 -> (row, 2*lc), c2,c3 -> (row+8, 2*lc)
    int r0 = rowBase + 16 * mw + lr;
#pragma unroll
    for (int nt = 0; nt < 4; nt++) {
        int c = 32 * nw + 8 * nt + 2 * lc;
        if (r0 < n_nodes)
            *reinterpret_cast<float2*>(&g_S1[r0 * NHID + c]) =
                make_float2(acc[nt][0], acc[nt][1]);
        if (r0 + 8 < n_nodes)
            *reinterpret_cast<float2*>(&g_S1[(r0 + 8) * NHID + c]) =
                make_float2(acc[nt][2], acc[nt][3]);
    }
}

// ---------------------------------------------------------------------------
// CSR build: zero (cnt + lookback state) -> histogram -> one-pass scan -> scatter
// ---------------------------------------------------------------------------
__global__ void zero_cnt_kernel(int n)
{
    int i = blockIdx.x * blockDim.x + threadIdx.x;
    if (i < n) g_cnt[i] = 0;
    if (i < 128) g_state[i] = 0;
}

__global__ void hist_kernel(const int* __restrict__ dst, int n_edges)
{
    int e = blockIdx.x * blockDim.x + threadIdx.x;
    if (e < n_edges) atomicAdd(&g_cnt[dst[e]], 1);
}

// Single-pass exclusive scan of g_cnt -> g_off/g_cur via decoupled lookback.
// Grid = ceil(n/512) (<=98 blocks, all resident -> no deadlock).
__global__ void __launch_bounds__(512) scan_onepass_kernel(int n)
{
    __shared__ int wsum[16];
    __shared__ int s_prefix;
    const int b = blockIdx.x;
    const int i = b * 512 + threadIdx.x;
    const int lane = threadIdx.x & 31, wid = threadIdx.x >> 5;

    int v = (i < n) ? g_cnt[i] : 0;
    int x = v;
#pragma unroll
    for (int o = 1; o < 32; o <<= 1) {
        int t = __shfl_up_sync(0xffffffffu, x, o);
        if (lane >= o) x += t;
    }
    if (lane == 31) wsum[wid] = x;
    __syncthreads();
    if (wid == 0) {
        int s = (lane < 16) ? wsum[lane] : 0;
#pragma unroll
        for (int o = 1; o < 16; o <<= 1) {
            int t = __shfl_up_sync(0xffffffffu, s, o);
            if (lane >= o) s += t;
        }
        if (lane < 16) wsum[lane] = s;
    }
    __syncthreads();
    const int base  = (wid > 0) ? wsum[wid - 1] : 0;
    const int total = wsum[15];

    // Publish this block's aggregate (block 0 publishes final prefix directly)
    if (threadIdx.x == 0)
        atomicExch(&g_state[b], (total << 2) | (b == 0 ? 2 : 1));

    // Warp 0: lookback over predecessors
    if (wid == 0) {
        int prefix = 0;
        if (b > 0) {
            int j = b - 1;
            while (true) {
                int idx = j - lane;
                int s = (idx >= 0) ? atomicAdd(&g_state[idx], 0) : 2; // virtual prefix 0
                if (__all_sync(0xffffffffu, (s & 3) != 0)) {
                    unsigned pm = __ballot_sync(0xffffffffu, (s & 3) == 2);
                    int cut = pm ? (__ffs(pm) - 1) : 32;
                    int val = (lane <= cut) ? (s >> 2) : 0;
#pragma unroll
                    for (int o = 16; o; o >>= 1)
                        val += __shfl_xor_sync(0xffffffffu, val, o);
                    prefix += val;
                    if (cut < 32) break;
                    j -= 32;
                }
            }
            if (lane == 0)
                atomicExch(&g_state[b], ((prefix + total) << 2) | 2);
        }
        if (lane == 0) s_prefix = prefix;
    }
    __syncthreads();

    int off = s_prefix + base + x - v;   // exclusive prefix
    if (i < n) { g_off[i] = off; g_cur[i] = off; }
}

__global__ void scatter_kernel(
    const int* __restrict__ src, const int* __restrict__ dst,
    const float* __restrict__ ew, int n_edges)
{
    int e = blockIdx.x * blockDim.x + threadIdx.x;
    if (e < n_edges) {
        int d = dst[e];
        int p = atomicAdd(&g_cur[d], 1);
        g_csr[p] = make_int2(src[e], __float_as_int(ew[e]));
    }
}

// ---------------------------------------------------------------------------
// SpMM1 (pull): H[d] = b1 + sum_e w_e * S1[src_e]  — warp per dst, no atomics.
// int4 loads fetch 2 CSR entries; 8-edge unroll for gather MLP.
// ---------------------------------------------------------------------------
__global__ void __launch_bounds__(256) spmm1_pull_kernel(
    const float* __restrict__ b1, int n_nodes)
{
    int lane = threadIdx.x & 31;
    int d = blockIdx.x * 8 + (threadIdx.x >> 5);
    if (d >= n_nodes) return;

    float2 acc = *reinterpret_cast<const float2*>(&b1[2 * lane]);
    int beg = g_off[d];
    int end = beg + g_cnt[d];
    int j = beg;

    if ((j & 1) && j < end) {        // align to int4 boundary
        int2 e = g_csr[j];
        float2 v = *reinterpret_cast<const float2*>(&g_S1[e.x * NHID + 2 * lane]);
        float wt = __int_as_float(e.y);
        acc.x = fmaf(wt, v.x, acc.x); acc.y = fmaf(wt, v.y, acc.y);
        j++;
    }
    const int4* csr4 = reinterpret_cast<const int4*>(g_csr);
    for (; j + 7 < end; j += 8) {
        int h = j >> 1;
        int4 p0 = csr4[h + 0], p1 = csr4[h + 1], p2 = csr4[h + 2], p3 = csr4[h + 3];
        float2 v0 = *reinterpret_cast<const float2*>(&g_S1[p0.x * NHID + 2 * lane]);
        float2 v1 = *reinterpret_cast<const float2*>(&g_S1[p0.z * NHID + 2 * lane]);
        float2 v2 = *reinterpret_cast<const float2*>(&g_S1[p1.x * NHID + 2 * lane]);
        float2 v3 = *reinterpret_cast<const float2*>(&g_S1[p1.z * NHID + 2 * lane]);
        float2 v4 = *reinterpret_cast<const float2*>(&g_S1[p2.x * NHID + 2 * lane]);
        float2 v5 = *reinterpret_cast<const float2*>(&g_S1[p2.z * NHID + 2 * lane]);
        float2 v6 = *reinterpret_cast<const float2*>(&g_S1[p3.x * NHID + 2 * lane]);
        float2 v7 = *reinterpret_cast<const float2*>(&g_S1[p3.z * NHID + 2 * lane]);
        float w0 = __int_as_float(p0.y), w1 = __int_as_float(p0.w);
        float w2 = __int_as_float(p1.y), w3 = __int_as_float(p1.w);
        float w4 = __int_as_float(p2.y), w5 = __int_as_float(p2.w);
        float w6 = __int_as_float(p3.y), w7 = __int_as_float(p3.w);
        acc.x = fmaf(w0, v0.x, acc.x); acc.y = fmaf(w0, v0.y, acc.y);
        acc.x = fmaf(w1, v1.x, acc.x); acc.y = fmaf(w1, v1.y, acc.y);
        acc.x = fmaf(w2, v2.x, acc.x); acc.y = fmaf(w2, v2.y, acc.y);
        acc.x = fmaf(w3, v3.x, acc.x); acc.y = fmaf(w3, v3.y, acc.y);
        acc.x = fmaf(w4, v4.x, acc.x); acc.y = fmaf(w4, v4.y, acc.y);
        acc.x = fmaf(w5, v5.x, acc.x); acc.y = fmaf(w5, v5.y, acc.y);
        acc.x = fmaf(w6, v6.x, acc.x); acc.y = fmaf(w6, v6.y, acc.y);
        acc.x = fmaf(w7, v7.x, acc.x); acc.y = fmaf(w7, v7.y, acc.y);
    }
    for (; j + 1 < end; j += 2) {
        int4 p = csr4[j >> 1];
        float2 v0 = *reinterpret_cast<const float2*>(&g_S1[p.x * NHID + 2 * lane]);
        float2 v1 = *reinterpret_cast<const float2*>(&g_S1[p.z * NHID + 2 * lane]);
        float w0 = __int_as_float(p.y), w1 = __int_as_float(p.w);
        acc.x = fmaf(w0, v0.x, acc.x); acc.y = fmaf(w0, v0.y, acc.y);
        acc.x = fmaf(w1, v1.x, acc.x); acc.y = fmaf(w1, v1.y, acc.y);
    }
    if (j < end) {
        int2 e = g_csr[j];
        float2 v = *reinterpret_cast<const float2*>(&g_S1[e.x * NHID + 2 * lane]);
        float wt = __int_as_float(e.y);
        acc.x = fmaf(wt, v.x, acc.x); acc.y = fmaf(wt, v.y, acc.y);
    }
    *reinterpret_cast<float2*>(&g_H[d * NHID + 2 * lane]) = acc;
}

// ---------------------------------------------------------------------------
// GEMM2 fused ReLU: S2[N,16] = relu(H)[N,64] @ W2[64,16]
// 128x16 tile, 256 threads, 2 rows x 4 cols per thread, plain FFMA.
// ---------------------------------------------------------------------------
__global__ void __launch_bounds__(256) gemm2_kernel(
    const float* __restrict__ W2, int n_nodes)
{
    __shared__ float hs[128][68];
    __shared__ float ws2[64][16];

    const int tid = threadIdx.x;
    const int tx = tid & 3;
    const int ty = tid >> 2;
    const int rowBase = blockIdx.x * 128;

#pragma unroll
    for (int j = 0; j < 8; j++) {
        int s = tid + j * 256;
        int r = s >> 4;
        int c4 = s & 15;
        float4 v = make_float4(0.f, 0.f, 0.f, 0.f);
        int grow = rowBase + r;
        if (grow < n_nodes)
            v = *reinterpret_cast<const float4*>(&g_H[grow * NHID + c4 * 4]);
        v.x = fmaxf(v.x, 0.f); v.y = fmaxf(v.y, 0.f);
        v.z = fmaxf(v.z, 0.f); v.w = fmaxf(v.w, 0.f);
        *reinterpret_cast<float4*>(&hs[r][c4 * 4]) = v;
    }
    {
        int kk = tid >> 2;
        int c4 = tid & 3;
        float4 v = *reinterpret_cast<const float4*>(&W2[kk * NCLASS + c4 * 4]);
        *reinterpret_cast<float4*>(&ws2[kk][c4 * 4]) = v;
    }
    __syncthreads();

    float acc0[4] = {0.f, 0.f, 0.f, 0.f};
    float acc1[4] = {0.f, 0.f, 0.f, 0.f};
#pragma unroll
    for (int kk = 0; kk < NHID; kk++) {
        float a0 = hs[ty][kk];
        float a1 = hs[ty + 64][kk];
        float4 w = *reinterpret_cast<const float4*>(&ws2[kk][4 * tx]);
        acc0[0] = fmaf(a0, w.x, acc0[0]); acc0[1] = fmaf(a0, w.y, acc0[1]);
        acc0[2] = fmaf(a0, w.z, acc0[2]); acc0[3] = fmaf(a0, w.w, acc0[3]);
        acc1[0] = fmaf(a1, w.x, acc1[0]); acc1[1] = fmaf(a1, w.y, acc1[1]);
        acc1[2] = fmaf(a1, w.z, acc1[2]); acc1[3] = fmaf(a1, w.w, acc1[3]);
    }

    int r0 = rowBase + ty, r1 = rowBase + ty + 64;
    if (r0 < n_nodes)
        *reinterpret_cast<float4*>(&g_S2[r0 * NCLASS + 4 * tx]) =
            make_float4(acc0[0], acc0[1], acc0[2], acc0[3]);
    if (r1 < n_nodes)
        *reinterpret_cast<float4*>(&g_S2[r1 * NCLASS + 4 * tx]) =
            make_float4(acc1[0], acc1[1], acc1[2], acc1[3]);
}

// ---------------------------------------------------------------------------
// SpMM2 (pull) + bias + log_softmax fused: out[d] = lsm(b2 + sum w*S2[src])
// 16 lanes per dst (1 class each); shfl reductions within 16-group.
// ---------------------------------------------------------------------------
__global__ void __launch_bounds__(256) spmm2_lsm_kernel(
    const float* __restrict__ b2, float* __restrict__ out, int n_nodes)
{
    int lane16 = threadIdx.x & 15;
    int d = blockIdx.x * 16 + (threadIdx.x >> 4);
    if (d >= n_nodes) return;

    float acc = b2[lane16];
    int beg = g_off[d];
    int end = beg + g_cnt[d];

    int j = beg;
    for (; j + 1 < end; j += 2) {
        int2 e0 = g_csr[j];
        int2 e1 = g_csr[j + 1];
        float v0 = g_S2[e0.x * NCLASS + lane16];
        float v1 = g_S2[e1.x * NCLASS + lane16];
        acc = fmaf(__int_as_float(e0.y), v0, acc);
        acc = fmaf(__int_as_float(e1.y), v1, acc);
    }
    if (j < end) {
        int2 e = g_csr[j];
        acc = fmaf(__int_as_float(e.y), g_S2[e.x * NCLASS + lane16], acc);
    }

    float m = acc;
#pragma unroll
    for (int o = 8; o >= 1; o >>= 1)
        m = fmaxf(m, __shfl_xor_sync(0xffffffffu, m, o, 16));
    float ssum = expf(acc - m);
#pragma unroll
    for (int o = 8; o >= 1; o >>= 1)
        ssum += __shfl_xor_sync(0xffffffffu, ssum, o, 16);
    out[d * NCLASS + lane16] = acc - m - logf(ssum);
}

// ---------------------------------------------------------------------------
// Launch.  Inputs: x, W1, b1, W2, b2, edge_src, edge_dst, edge_weight
// ---------------------------------------------------------------------------
extern "C" void kernel_launch(void* const* d_in, const int* in_sizes, int n_in,
                              void* d_out, int out_size)
{
    const float* x    = (const float*)d_in[0];
    const float* W1   = (const float*)d_in[1];
    const float* b1   = (const float*)d_in[2];
    const float* W2   = (const float*)d_in[3];
    const float* b2   = (const float*)d_in[4];
    const int*   esrc = (const int*)d_in[5];
    const int*   edst = (const int*)d_in[6];
    const float* ew   = (const float*)d_in[7];

    int n_nodes = in_sizes[0] / NFEAT;
    int n_edges = in_sizes[5];
    int nb = (n_nodes + 511) / 512;

    // CSR-by-dst build
    zero_cnt_kernel<<<(n_nodes + 255) / 256, 256>>>(n_nodes);
    hist_kernel<<<(n_edges + 255) / 256, 256>>>(edst, n_edges);
    scan_onepass_kernel<<<nb, 512>>>(n_nodes);
    scatter_kernel<<<(n_edges + 255) / 256, 256>>>(esrc, edst, ew, n_edges);

    // GEMM1 (tf32 tensor cores)
    gemm1_tf32_kernel<<<(n_nodes + 63) / 64, 256>>>(x, W1, n_nodes);

    // Layer 1 aggregate (pull, warp/dst, no atomics)
    spmm1_pull_kernel<<<(n_nodes + 7) / 8, 256>>>(b1, n_nodes);

    // Layer 2
    gemm2_kernel<<<(n_nodes + 127) / 128, 256>>>(W2, n_nodes);
    spmm2_lsm_kernel<<<(n_nodes + 15) / 16, 256>>>(b2, (float*)d_out, n_nodes);
}

// round 11
// speedup vs baseline: 1.9644x; 1.0333x over previous
#include <cuda_runtime.h>
#include <cuda_bf16.h>
#include <cuda_fp16.h>
#include <math.h>

#define NFEAT   256
#define NHID    64
#define NCLASS  16
#define MAXN    50000
#define MAXE    1600000

// ---------------------------------------------------------------------------
// Scratch (allocation-free device globals)
// ---------------------------------------------------------------------------
__device__ __align__(16) __half g_S1h[MAXN * NHID];    // x @ W1      (fp16)
__device__ __align__(16) float  g_H  [MAXN * NHID];    // spmm1 + b1  (fp32)
__device__ __align__(16) __half g_S2h[MAXN * NCLASS];  // relu(H)@W2  (fp16)

__device__ int  g_cnt[MAXN];            // in-degree per dst
__device__ int  g_off[MAXN];            // CSR row offsets
__device__ int  g_rank[MAXE];           // per-edge rank within its dst bucket
__device__ int  g_state[128];           // decoupled-lookback state: (sum<<2)|flag
__device__ __align__(16) int2 g_csr[MAXE];   // packed (src, w-bits), grouped by dst

// ---------------------------------------------------------------------------
// GEMM1 via tf32 tensor cores: S1[N,64] = x[N,256] @ W1[256,64], fp16 output
// 64x64 tile / block (256 thr, 8 warps). Warp w -> m-tile (w>>1)*16, n-half (w&1)*32.
// ---------------------------------------------------------------------------
__device__ __forceinline__ unsigned f2tf32(float f) {
    unsigned u;
    asm("cvt.rna.tf32.f32 %0, %1;" : "=r"(u) : "f"(f));
    return u;
}

__global__ void __launch_bounds__(256) gemm1_tf32_kernel(
    const float* __restrict__ x, const float* __restrict__ W1, int n_nodes)
{
    __shared__ unsigned xs[64][36];
    __shared__ unsigned ws[32][72];

    const int tid = threadIdx.x;
    const int w   = tid >> 5;
    const int lane = tid & 31;
    const int mw = w >> 1;
    const int nw = w & 1;
    const int lr = lane >> 2;
    const int lc = lane & 3;
    const int rowBase = blockIdx.x * 64;

    float acc[4][4];
#pragma unroll
    for (int i = 0; i < 4; i++)
#pragma unroll
        for (int j = 0; j < 4; j++) acc[i][j] = 0.f;

#pragma unroll 1
    for (int k0 = 0; k0 < NFEAT; k0 += 32) {
#pragma unroll
        for (int j = 0; j < 2; j++) {
            int s = tid * 2 + j;
            int r = s >> 3;
            int c4 = s & 7;
            float4 v = make_float4(0.f, 0.f, 0.f, 0.f);
            int grow = rowBase + r;
            if (grow < n_nodes)
                v = *reinterpret_cast<const float4*>(&x[grow * NFEAT + k0 + c4 * 4]);
            xs[r][c4 * 4 + 0] = f2tf32(v.x);
            xs[r][c4 * 4 + 1] = f2tf32(v.y);
            xs[r][c4 * 4 + 2] = f2tf32(v.z);
            xs[r][c4 * 4 + 3] = f2tf32(v.w);
        }
#pragma unroll
        for (int j = 0; j < 2; j++) {
            int s = tid * 2 + j;
            int kk = s >> 4;
            int c4 = s & 15;
            float4 v = *reinterpret_cast<const float4*>(&W1[(k0 + kk) * NHID + c4 * 4]);
            ws[kk][c4 * 4 + 0] = f2tf32(v.x);
            ws[kk][c4 * 4 + 1] = f2tf32(v.y);
            ws[kk][c4 * 4 + 2] = f2tf32(v.z);
            ws[kk][c4 * 4 + 3] = f2tf32(v.w);
        }
        __syncthreads();

#pragma unroll
        for (int k8 = 0; k8 < 32; k8 += 8) {
            unsigned a0 = xs[16 * mw + lr    ][k8 + lc    ];
            unsigned a1 = xs[16 * mw + lr + 8][k8 + lc    ];
            unsigned a2 = xs[16 * mw + lr    ][k8 + lc + 4];
            unsigned a3 = xs[16 * mw + lr + 8][k8 + lc + 4];
#pragma unroll
            for (int nt = 0; nt < 4; nt++) {
                int ncol = 32 * nw + 8 * nt + lr;
                unsigned b0 = ws[k8 + lc    ][ncol];
                unsigned b1 = ws[k8 + lc + 4][ncol];
                asm volatile(
                    "mma.sync.aligned.m16n8k8.row.col.f32.tf32.tf32.f32 "
                    "{%0,%1,%2,%3}, {%4,%5,%6,%7}, {%8,%9}, {%0,%1,%2,%3};"
                    : "+f"(acc[nt][0]), "+f"(acc[nt][1]),
                      "+f"(acc[nt][2]), "+f"(acc[nt][3])
                    : "r"(a0), "r"(a1), "r"(a2), "r"(a3), "r"(b0), "r"(b1));
            }
        }
        __syncthreads();
    }

    int r0 = rowBase + 16 * mw + lr;
#pragma unroll
    for (int nt = 0; nt < 4; nt++) {
        int c = 32 * nw + 8 * nt + 2 * lc;
        if (r0 < n_nodes)
            *reinterpret_cast<__half2*>(&g_S1h[r0 * NHID + c]) =
                __floats2half2_rn(acc[nt][0], acc[nt][1]);
        if (r0 + 8 < n_nodes)
            *reinterpret_cast<__half2*>(&g_S1h[(r0 + 8) * NHID + c]) =
                __floats2half2_rn(acc[nt][2], acc[nt][3]);
    }
}

// ---------------------------------------------------------------------------
// CSR build: zero -> histogram(+rank) -> one-pass scan -> atomic-free scatter
// ---------------------------------------------------------------------------
__global__ void zero_cnt_kernel(int n)
{
    int i = blockIdx.x * blockDim.x + threadIdx.x;
    if (i < n) g_cnt[i] = 0;
    if (i < 128) g_state[i] = 0;
}

// Histogram; also records each edge's arrival rank within its dst bucket.
__global__ void hist_rank_kernel(const int* __restrict__ dst, int n_edges)
{
    int e = blockIdx.x * blockDim.x + threadIdx.x;
    if (e < n_edges)
        g_rank[e] = atomicAdd(&g_cnt[dst[e]], 1);
}

// Single-pass exclusive scan of g_cnt -> g_off via decoupled lookback.
__global__ void __launch_bounds__(512) scan_onepass_kernel(int n)
{
    __shared__ int wsum[16];
    __shared__ int s_prefix;
    const int b = blockIdx.x;
    const int i = b * 512 + threadIdx.x;
    const int lane = threadIdx.x & 31, wid = threadIdx.x >> 5;

    int v = (i < n) ? g_cnt[i] : 0;
    int x = v;
#pragma unroll
    for (int o = 1; o < 32; o <<= 1) {
        int t = __shfl_up_sync(0xffffffffu, x, o);
        if (lane >= o) x += t;
    }
    if (lane == 31) wsum[wid] = x;
    __syncthreads();
    if (wid == 0) {
        int s = (lane < 16) ? wsum[lane] : 0;
#pragma unroll
        for (int o = 1; o < 16; o <<= 1) {
            int t = __shfl_up_sync(0xffffffffu, s, o);
            if (lane >= o) s += t;
        }
        if (lane < 16) wsum[lane] = s;
    }
    __syncthreads();
    const int base  = (wid > 0) ? wsum[wid - 1] : 0;
    const int total = wsum[15];

    if (threadIdx.x == 0)
        atomicExch(&g_state[b], (total << 2) | (b == 0 ? 2 : 1));

    if (wid == 0) {
        int prefix = 0;
        if (b > 0) {
            int j = b - 1;
            while (true) {
                int idx = j - lane;
                int s = (idx >= 0) ? atomicAdd(&g_state[idx], 0) : 2;
                if (__all_sync(0xffffffffu, (s & 3) != 0)) {
                    unsigned pm = __ballot_sync(0xffffffffu, (s & 3) == 2);
                    int cut = pm ? (__ffs(pm) - 1) : 32;
                    int val = (lane <= cut) ? (s >> 2) : 0;
#pragma unroll
                    for (int o = 16; o; o >>= 1)
                        val += __shfl_xor_sync(0xffffffffu, val, o);
                    prefix += val;
                    if (cut < 32) break;
                    j -= 32;
                }
            }
            if (lane == 0)
                atomicExch(&g_state[b], ((prefix + total) << 2) | 2);
        }
        if (lane == 0) s_prefix = prefix;
    }
    __syncthreads();

    int off = s_prefix + base + x - v;
    if (i < n) g_off[i] = off;
}

// Atomic-free scatter: position = off[dst] + rank[e]
__global__ void scatter_kernel(
    const int* __restrict__ src, const int* __restrict__ dst,
    const float* __restrict__ ew, int n_edges)
{
    int e = blockIdx.x * blockDim.x + threadIdx.x;
    if (e < n_edges) {
        int d = dst[e];
        int p = g_off[d] + g_rank[e];
        g_csr[p] = make_int2(src[e], __float_as_int(ew[e]));
    }
}

// ---------------------------------------------------------------------------
// SpMM1 (pull): H[d] = b1 + sum_e w_e * S1[src_e]  — warp per dst, no atomics.
// S1 is fp16: lane reads half2 (2 feats), fp32 accumulate. 8-edge unroll.
// ---------------------------------------------------------------------------
__global__ void __launch_bounds__(256) spmm1_pull_kernel(
    const float* __restrict__ b1, int n_nodes)
{
    int lane = threadIdx.x & 31;
    int d = blockIdx.x * 8 + (threadIdx.x >> 5);
    if (d >= n_nodes) return;

    float2 acc = *reinterpret_cast<const float2*>(&b1[2 * lane]);
    int beg = g_off[d];
    int end = beg + g_cnt[d];
    int j = beg;

    if ((j & 1) && j < end) {
        int2 e = g_csr[j];
        float2 v = __half22float2(*reinterpret_cast<const __half2*>(&g_S1h[e.x * NHID + 2 * lane]));
        float wt = __int_as_float(e.y);
        acc.x = fmaf(wt, v.x, acc.x); acc.y = fmaf(wt, v.y, acc.y);
        j++;
    }
    const int4* csr4 = reinterpret_cast<const int4*>(g_csr);
    for (; j + 7 < end; j += 8) {
        int h = j >> 1;
        int4 p0 = csr4[h + 0], p1 = csr4[h + 1], p2 = csr4[h + 2], p3 = csr4[h + 3];
        float2 v0 = __half22float2(*reinterpret_cast<const __half2*>(&g_S1h[p0.x * NHID + 2 * lane]));
        float2 v1 = __half22float2(*reinterpret_cast<const __half2*>(&g_S1h[p0.z * NHID + 2 * lane]));
        float2 v2 = __half22float2(*reinterpret_cast<const __half2*>(&g_S1h[p1.x * NHID + 2 * lane]));
        float2 v3 = __half22float2(*reinterpret_cast<const __half2*>(&g_S1h[p1.z * NHID + 2 * lane]));
        float2 v4 = __half22float2(*reinterpret_cast<const __half2*>(&g_S1h[p2.x * NHID + 2 * lane]));
        float2 v5 = __half22float2(*reinterpret_cast<const __half2*>(&g_S1h[p2.z * NHID + 2 * lane]));
        float2 v6 = __half22float2(*reinterpret_cast<const __half2*>(&g_S1h[p3.x * NHID + 2 * lane]));
        float2 v7 = __half22float2(*reinterpret_cast<const __half2*>(&g_S1h[p3.z * NHID + 2 * lane]));
        float w0 = __int_as_float(p0.y), w1 = __int_as_float(p0.w);
        float w2 = __int_as_float(p1.y), w3 = __int_as_float(p1.w);
        float w4 = __int_as_float(p2.y), w5 = __int_as_float(p2.w);
        float w6 = __int_as_float(p3.y), w7 = __int_as_float(p3.w);
        acc.x = fmaf(w0, v0.x, acc.x); acc.y = fmaf(w0, v0.y, acc.y);
        acc.x = fmaf(w1, v1.x, acc.x); acc.y = fmaf(w1, v1.y, acc.y);
        acc.x = fmaf(w2, v2.x, acc.x); acc.y = fmaf(w2, v2.y, acc.y);
        acc.x = fmaf(w3, v3.x, acc.x); acc.y = fmaf(w3, v3.y, acc.y);
        acc.x = fmaf(w4, v4.x, acc.x); acc.y = fmaf(w4, v4.y, acc.y);
        acc.x = fmaf(w5, v5.x, acc.x); acc.y = fmaf(w5, v5.y, acc.y);
        acc.x = fmaf(w6, v6.x, acc.x); acc.y = fmaf(w6, v6.y, acc.y);
        acc.x = fmaf(w7, v7.x, acc.x); acc.y = fmaf(w7, v7.y, acc.y);
    }
    for (; j + 1 < end; j += 2) {
        int4 p = csr4[j >> 1];
        float2 v0 = __half22float2(*reinterpret_cast<const __half2*>(&g_S1h[p.x * NHID + 2 * lane]));
        float2 v1 = __half22float2(*reinterpret_cast<const __half2*>(&g_S1h[p.z * NHID + 2 * lane]));
        float w0 = __int_as_float(p.y), w1 = __int_as_float(p.w);
        acc.x = fmaf(w0, v0.x, acc.x); acc.y = fmaf(w0, v0.y, acc.y);
        acc.x = fmaf(w1, v1.x, acc.x); acc.y = fmaf(w1, v1.y, acc.y);
    }
    if (j < end) {
        int2 e = g_csr[j];
        float2 v = __half22float2(*reinterpret_cast<const __half2*>(&g_S1h[e.x * NHID + 2 * lane]));
        float wt = __int_as_float(e.y);
        acc.x = fmaf(wt, v.x, acc.x); acc.y = fmaf(wt, v.y, acc.y);
    }
    *reinterpret_cast<float2*>(&g_H[d * NHID + 2 * lane]) = acc;
}

// ---------------------------------------------------------------------------
// GEMM2 fused ReLU: S2[N,16] = relu(H)[N,64] @ W2[64,16], fp16 output
// ---------------------------------------------------------------------------
__global__ void __launch_bounds__(256) gemm2_kernel(
    const float* __restrict__ W2, int n_nodes)
{
    __shared__ float hs[128][68];
    __shared__ float ws2[64][16];

    const int tid = threadIdx.x;
    const int tx = tid & 3;
    const int ty = tid >> 2;
    const int rowBase = blockIdx.x * 128;

#pragma unroll
    for (int j = 0; j < 8; j++) {
        int s = tid + j * 256;
        int r = s >> 4;
        int c4 = s & 15;
        float4 v = make_float4(0.f, 0.f, 0.f, 0.f);
        int grow = rowBase + r;
        if (grow < n_nodes)
            v = *reinterpret_cast<const float4*>(&g_H[grow * NHID + c4 * 4]);
        v.x = fmaxf(v.x, 0.f); v.y = fmaxf(v.y, 0.f);
        v.z = fmaxf(v.z, 0.f); v.w = fmaxf(v.w, 0.f);
        *reinterpret_cast<float4*>(&hs[r][c4 * 4]) = v;
    }
    {
        int kk = tid >> 2;
        int c4 = tid & 3;
        float4 v = *reinterpret_cast<const float4*>(&W2[kk * NCLASS + c4 * 4]);
        *reinterpret_cast<float4*>(&ws2[kk][c4 * 4]) = v;
    }
    __syncthreads();

    float acc0[4] = {0.f, 0.f, 0.f, 0.f};
    float acc1[4] = {0.f, 0.f, 0.f, 0.f};
#pragma unroll
    for (int kk = 0; kk < NHID; kk++) {
        float a0 = hs[ty][kk];
        float a1 = hs[ty + 64][kk];
        float4 w = *reinterpret_cast<const float4*>(&ws2[kk][4 * tx]);
        acc0[0] = fmaf(a0, w.x, acc0[0]); acc0[1] = fmaf(a0, w.y, acc0[1]);
        acc0[2] = fmaf(a0, w.z, acc0[2]); acc0[3] = fmaf(a0, w.w, acc0[3]);
        acc1[0] = fmaf(a1, w.x, acc1[0]); acc1[1] = fmaf(a1, w.y, acc1[1]);
        acc1[2] = fmaf(a1, w.z, acc1[2]); acc1[3] = fmaf(a1, w.w, acc1[3]);
    }

    int r0 = rowBase + ty, r1 = rowBase + ty + 64;
    if (r0 < n_nodes) {
        __half2 h2[2] = { __floats2half2_rn(acc0[0], acc0[1]),
                          __floats2half2_rn(acc0[2], acc0[3]) };
        *reinterpret_cast<uint2*>(&g_S2h[r0 * NCLASS + 4 * tx]) =
            *reinterpret_cast<const uint2*>(h2);
    }
    if (r1 < n_nodes) {
        __half2 h2[2] = { __floats2half2_rn(acc1[0], acc1[1]),
                          __floats2half2_rn(acc1[2], acc1[3]) };
        *reinterpret_cast<uint2*>(&g_S2h[r1 * NCLASS + 4 * tx]) =
            *reinterpret_cast<const uint2*>(h2);
    }
}

// ---------------------------------------------------------------------------
// SpMM2 (pull) + bias + log_softmax fused: out[d] = lsm(b2 + sum w*S2[src])
// 16 lanes per dst (1 class each); int4 CSR loads, 4-edge unroll.
// ---------------------------------------------------------------------------
__global__ void __launch_bounds__(256) spmm2_lsm_kernel(
    const float* __restrict__ b2, float* __restrict__ out, int n_nodes)
{
    int lane16 = threadIdx.x & 15;
    int d = blockIdx.x * 16 + (threadIdx.x >> 4);
    if (d >= n_nodes) return;

    float acc = b2[lane16];
    int beg = g_off[d];
    int end = beg + g_cnt[d];
    int j = beg;

    if ((j & 1) && j < end) {
        int2 e = g_csr[j];
        acc = fmaf(__int_as_float(e.y), __half2float(g_S2h[e.x * NCLASS + lane16]), acc);
        j++;
    }
    const int4* csr4 = reinterpret_cast<const int4*>(g_csr);
    for (; j + 3 < end; j += 4) {
        int h = j >> 1;
        int4 p0 = csr4[h], p1 = csr4[h + 1];
        float v0 = __half2float(g_S2h[p0.x * NCLASS + lane16]);
        float v1 = __half2float(g_S2h[p0.z * NCLASS + lane16]);
        float v2 = __half2float(g_S2h[p1.x * NCLASS + lane16]);
        float v3 = __half2float(g_S2h[p1.z * NCLASS + lane16]);
        acc = fmaf(__int_as_float(p0.y), v0, acc);
        acc = fmaf(__int_as_float(p0.w), v1, acc);
        acc = fmaf(__int_as_float(p1.y), v2, acc);
        acc = fmaf(__int_as_float(p1.w), v3, acc);
    }
    for (; j < end; j++) {
        int2 e = g_csr[j];
        acc = fmaf(__int_as_float(e.y), __half2float(g_S2h[e.x * NCLASS + lane16]), acc);
    }

    float m = acc;
#pragma unroll
    for (int o = 8; o >= 1; o >>= 1)
        m = fmaxf(m, __shfl_xor_sync(0xffffffffu, m, o, 16));
    float ssum = expf(acc - m);
#pragma unroll
    for (int o = 8; o >= 1; o >>= 1)
        ssum += __shfl_xor_sync(0xffffffffu, ssum, o, 16);
    out[d * NCLASS + lane16] = acc - m - logf(ssum);
}

// ---------------------------------------------------------------------------
// Launch.  Inputs: x, W1, b1, W2, b2, edge_src, edge_dst, edge_weight
// ---------------------------------------------------------------------------
extern "C" void kernel_launch(void* const* d_in, const int* in_sizes, int n_in,
                              void* d_out, int out_size)
{
    const float* x    = (const float*)d_in[0];
    const float* W1   = (const float*)d_in[1];
    const float* b1   = (const float*)d_in[2];
    const float* W2   = (const float*)d_in[3];
    const float* b2   = (const float*)d_in[4];
    const int*   esrc = (const int*)d_in[5];
    const int*   edst = (const int*)d_in[6];
    const float* ew   = (const float*)d_in[7];

    int n_nodes = in_sizes[0] / NFEAT;
    int n_edges = in_sizes[5];
    int nb = (n_nodes + 511) / 512;

    // CSR-by-dst build
    zero_cnt_kernel<<<(n_nodes + 255) / 256, 256>>>(n_nodes);
    hist_rank_kernel<<<(n_edges + 255) / 256, 256>>>(edst, n_edges);
    scan_onepass_kernel<<<nb, 512>>>(n_nodes);
    scatter_kernel<<<(n_edges + 255) / 256, 256>>>(esrc, edst, ew, n_edges);

    // GEMM1 (tf32 tensor cores, fp16 out)
    gemm1_tf32_kernel<<<(n_nodes + 63) / 64, 256>>>(x, W1, n_nodes);

    // Layer 1 aggregate (pull, warp/dst, no atomics)
    spmm1_pull_kernel<<<(n_nodes + 7) / 8, 256>>>(b1, n_nodes);

    // Layer 2
    gemm2_kernel<<<(n_nodes + 127) / 128, 256>>>(W2, n_nodes);
    spmm2_lsm_kernel<<<(n_nodes + 15) / 16, 256>>>(b2, (float*)d_out, n_nodes);
}

// round 12
// speedup vs baseline: 2.1644x; 1.1018x over previous
#include <cuda_runtime.h>
#include <cuda_bf16.h>
#include <cuda_fp16.h>
#include <math.h>

#define NFEAT   256
#define NHID    64
#define NCLASS  16
#define MAXN    50000
#define MAXE    1600000

// ---------------------------------------------------------------------------
// Scratch (allocation-free device globals)
// ---------------------------------------------------------------------------
__device__ __align__(16) __half g_S1h[MAXN * NHID];    // x @ W1      (fp16)
__device__ __align__(16) float  g_H  [MAXN * NHID];    // spmm1 + b1  (fp32)
__device__ __align__(16) __half g_S2h[MAXN * NCLASS];  // relu(H)@W2  (fp16)

__device__ __align__(16) int  g_cnt[MAXN];      // in-degree per dst
__device__ __align__(16) int  g_off[MAXN];      // CSR row offsets
__device__ __align__(16) int  g_rank[MAXE];     // per-edge rank within dst bucket
__device__ int  g_state[128];                   // decoupled-lookback state
__device__ __align__(16) int2 g_csr[MAXE];      // packed (src, w-bits), by dst

// ---------------------------------------------------------------------------
// GEMM1 via tf32 tensor cores: S1[N,64] = x[N,256] @ W1[256,64], fp16 output
// ---------------------------------------------------------------------------
__device__ __forceinline__ unsigned f2tf32(float f) {
    unsigned u;
    asm("cvt.rna.tf32.f32 %0, %1;" : "=r"(u) : "f"(f));
    return u;
}

__global__ void __launch_bounds__(256) gemm1_tf32_kernel(
    const float* __restrict__ x, const float* __restrict__ W1, int n_nodes)
{
    __shared__ unsigned xs[64][36];
    __shared__ unsigned ws[32][72];

    const int tid = threadIdx.x;
    const int w   = tid >> 5;
    const int lane = tid & 31;
    const int mw = w >> 1;
    const int nw = w & 1;
    const int lr = lane >> 2;
    const int lc = lane & 3;
    const int rowBase = blockIdx.x * 64;

    float acc[4][4];
#pragma unroll
    for (int i = 0; i < 4; i++)
#pragma unroll
        for (int j = 0; j < 4; j++) acc[i][j] = 0.f;

#pragma unroll 1
    for (int k0 = 0; k0 < NFEAT; k0 += 32) {
#pragma unroll
        for (int j = 0; j < 2; j++) {
            int s = tid * 2 + j;
            int r = s >> 3;
            int c4 = s & 7;
            float4 v = make_float4(0.f, 0.f, 0.f, 0.f);
            int grow = rowBase + r;
            if (grow < n_nodes)
                v = *reinterpret_cast<const float4*>(&x[grow * NFEAT + k0 + c4 * 4]);
            xs[r][c4 * 4 + 0] = f2tf32(v.x);
            xs[r][c4 * 4 + 1] = f2tf32(v.y);
            xs[r][c4 * 4 + 2] = f2tf32(v.z);
            xs[r][c4 * 4 + 3] = f2tf32(v.w);
        }
#pragma unroll
        for (int j = 0; j < 2; j++) {
            int s = tid * 2 + j;
            int kk = s >> 4;
            int c4 = s & 15;
            float4 v = *reinterpret_cast<const float4*>(&W1[(k0 + kk) * NHID + c4 * 4]);
            ws[kk][c4 * 4 + 0] = f2tf32(v.x);
            ws[kk][c4 * 4 + 1] = f2tf32(v.y);
            ws[kk][c4 * 4 + 2] = f2tf32(v.z);
            ws[kk][c4 * 4 + 3] = f2tf32(v.w);
        }
        __syncthreads();

#pragma unroll
        for (int k8 = 0; k8 < 32; k8 += 8) {
            unsigned a0 = xs[16 * mw + lr    ][k8 + lc    ];
            unsigned a1 = xs[16 * mw + lr + 8][k8 + lc    ];
            unsigned a2 = xs[16 * mw + lr    ][k8 + lc + 4];
            unsigned a3 = xs[16 * mw + lr + 8][k8 + lc + 4];
#pragma unroll
            for (int nt = 0; nt < 4; nt++) {
                int ncol = 32 * nw + 8 * nt + lr;
                unsigned b0 = ws[k8 + lc    ][ncol];
                unsigned b1 = ws[k8 + lc + 4][ncol];
                asm volatile(
                    "mma.sync.aligned.m16n8k8.row.col.f32.tf32.tf32.f32 "
                    "{%0,%1,%2,%3}, {%4,%5,%6,%7}, {%8,%9}, {%0,%1,%2,%3};"
                    : "+f"(acc[nt][0]), "+f"(acc[nt][1]),
                      "+f"(acc[nt][2]), "+f"(acc[nt][3])
                    : "r"(a0), "r"(a1), "r"(a2), "r"(a3), "r"(b0), "r"(b1));
            }
        }
        __syncthreads();
    }

    int r0 = rowBase + 16 * mw + lr;
#pragma unroll
    for (int nt = 0; nt < 4; nt++) {
        int c = 32 * nw + 8 * nt + 2 * lc;
        if (r0 < n_nodes)
            *reinterpret_cast<__half2*>(&g_S1h[r0 * NHID + c]) =
                __floats2half2_rn(acc[nt][0], acc[nt][1]);
        if (r0 + 8 < n_nodes)
            *reinterpret_cast<__half2*>(&g_S1h[(r0 + 8) * NHID + c]) =
                __floats2half2_rn(acc[nt][2], acc[nt][3]);
    }
}

// ---------------------------------------------------------------------------
// CSR build: zero -> histogram(+rank, x4) -> one-pass scan -> scatter (x4)
// ---------------------------------------------------------------------------
__global__ void zero_cnt_kernel(int n4)   // n4 = ceil(n/4)
{
    int i = blockIdx.x * blockDim.x + threadIdx.x;
    if (i < n4)
        *reinterpret_cast<int4*>(&g_cnt[i * 4]) = make_int4(0, 0, 0, 0);
    if (i < 128) g_state[i] = 0;
}

// Histogram; records each edge's arrival rank. 4 edges/thread for atomic MLP.
__global__ void hist_rank_kernel(const int* __restrict__ dst, int n_edges)
{
    int t = blockIdx.x * blockDim.x + threadIdx.x;
    int e = t * 4;
    if (e + 3 < n_edges) {
        int4 d = *reinterpret_cast<const int4*>(&dst[e]);
        int r0 = atomicAdd(&g_cnt[d.x], 1);
        int r1 = atomicAdd(&g_cnt[d.y], 1);
        int r2 = atomicAdd(&g_cnt[d.z], 1);
        int r3 = atomicAdd(&g_cnt[d.w], 1);
        *reinterpret_cast<int4*>(&g_rank[e]) = make_int4(r0, r1, r2, r3);
    } else {
        for (; e < n_edges; e++)
            g_rank[e] = atomicAdd(&g_cnt[dst[e]], 1);
    }
}

// Single-pass exclusive scan of g_cnt -> g_off via decoupled lookback.
__global__ void __launch_bounds__(512) scan_onepass_kernel(int n)
{
    __shared__ int wsum[16];
    __shared__ int s_prefix;
    const int b = blockIdx.x;
    const int i = b * 512 + threadIdx.x;
    const int lane = threadIdx.x & 31, wid = threadIdx.x >> 5;

    int v = (i < n) ? g_cnt[i] : 0;
    int x = v;
#pragma unroll
    for (int o = 1; o < 32; o <<= 1) {
        int t = __shfl_up_sync(0xffffffffu, x, o);
        if (lane >= o) x += t;
    }
    if (lane == 31) wsum[wid] = x;
    __syncthreads();
    if (wid == 0) {
        int s = (lane < 16) ? wsum[lane] : 0;
#pragma unroll
        for (int o = 1; o < 16; o <<= 1) {
            int t = __shfl_up_sync(0xffffffffu, s, o);
            if (lane >= o) s += t;
        }
        if (lane < 16) wsum[lane] = s;
    }
    __syncthreads();
    const int base  = (wid > 0) ? wsum[wid - 1] : 0;
    const int total = wsum[15];

    if (threadIdx.x == 0)
        atomicExch(&g_state[b], (total << 2) | (b == 0 ? 2 : 1));

    if (wid == 0) {
        int prefix = 0;
        if (b > 0) {
            int j = b - 1;
            while (true) {
                int idx = j - lane;
                int s = (idx >= 0) ? atomicAdd(&g_state[idx], 0) : 2;
                if (__all_sync(0xffffffffu, (s & 3) != 0)) {
                    unsigned pm = __ballot_sync(0xffffffffu, (s & 3) == 2);
                    int cut = pm ? (__ffs(pm) - 1) : 32;
                    int val = (lane <= cut) ? (s >> 2) : 0;
#pragma unroll
                    for (int o = 16; o; o >>= 1)
                        val += __shfl_xor_sync(0xffffffffu, val, o);
                    prefix += val;
                    if (cut < 32) break;
                    j -= 32;
                }
            }
            if (lane == 0)
                atomicExch(&g_state[b], ((prefix + total) << 2) | 2);
        }
        if (lane == 0) s_prefix = prefix;
    }
    __syncthreads();

    int off = s_prefix + base + x - v;
    if (i < n) g_off[i] = off;
}

// Atomic-free scatter, 4 edges/thread: position = off[dst] + rank[e]; MLP=4
__global__ void scatter_kernel(
    const int* __restrict__ src, const int* __restrict__ dst,
    const float* __restrict__ ew, int n_edges)
{
    int t = blockIdx.x * blockDim.x + threadIdx.x;
    int e = t * 4;
    if (e + 3 < n_edges) {
        int4   d = *reinterpret_cast<const int4*>(&dst[e]);
        int4   s = *reinterpret_cast<const int4*>(&src[e]);
        int4   r = *reinterpret_cast<const int4*>(&g_rank[e]);
        float4 w = *reinterpret_cast<const float4*>(&ew[e]);
        int o0 = g_off[d.x], o1 = g_off[d.y], o2 = g_off[d.z], o3 = g_off[d.w];
        g_csr[o0 + r.x] = make_int2(s.x, __float_as_int(w.x));
        g_csr[o1 + r.y] = make_int2(s.y, __float_as_int(w.y));
        g_csr[o2 + r.z] = make_int2(s.z, __float_as_int(w.z));
        g_csr[o3 + r.w] = make_int2(s.w, __float_as_int(w.w));
    } else {
        for (; e < n_edges; e++) {
            int d = dst[e];
            g_csr[g_off[d] + g_rank[e]] = make_int2(src[e], __float_as_int(ew[e]));
        }
    }
}

// ---------------------------------------------------------------------------
// SpMM1 (pull): H[d] = b1 + sum_e w_e * S1[src_e]  — warp per dst, no atomics.
// S1 fp16: lane reads half2, fp32 accumulate. 8-edge unroll.
// ---------------------------------------------------------------------------
__global__ void __launch_bounds__(256) spmm1_pull_kernel(
    const float* __restrict__ b1, int n_nodes)
{
    int lane = threadIdx.x & 31;
    int d = blockIdx.x * 8 + (threadIdx.x >> 5);
    if (d >= n_nodes) return;

    float2 acc = *reinterpret_cast<const float2*>(&b1[2 * lane]);
    int beg = g_off[d];
    int end = beg + g_cnt[d];
    int j = beg;

    if ((j & 1) && j < end) {
        int2 e = g_csr[j];
        float2 v = __half22float2(*reinterpret_cast<const __half2*>(&g_S1h[e.x * NHID + 2 * lane]));
        float wt = __int_as_float(e.y);
        acc.x = fmaf(wt, v.x, acc.x); acc.y = fmaf(wt, v.y, acc.y);
        j++;
    }
    const int4* csr4 = reinterpret_cast<const int4*>(g_csr);
    for (; j + 7 < end; j += 8) {
        int h = j >> 1;
        int4 p0 = csr4[h + 0], p1 = csr4[h + 1], p2 = csr4[h + 2], p3 = csr4[h + 3];
        float2 v0 = __half22float2(*reinterpret_cast<const __half2*>(&g_S1h[p0.x * NHID + 2 * lane]));
        float2 v1 = __half22float2(*reinterpret_cast<const __half2*>(&g_S1h[p0.z * NHID + 2 * lane]));
        float2 v2 = __half22float2(*reinterpret_cast<const __half2*>(&g_S1h[p1.x * NHID + 2 * lane]));
        float2 v3 = __half22float2(*reinterpret_cast<const __half2*>(&g_S1h[p1.z * NHID + 2 * lane]));
        float2 v4 = __half22float2(*reinterpret_cast<const __half2*>(&g_S1h[p2.x * NHID + 2 * lane]));
        float2 v5 = __half22float2(*reinterpret_cast<const __half2*>(&g_S1h[p2.z * NHID + 2 * lane]));
        float2 v6 = __half22float2(*reinterpret_cast<const __half2*>(&g_S1h[p3.x * NHID + 2 * lane]));
        float2 v7 = __half22float2(*reinterpret_cast<const __half2*>(&g_S1h[p3.z * NHID + 2 * lane]));
        float w0 = __int_as_float(p0.y), w1 = __int_as_float(p0.w);
        float w2 = __int_as_float(p1.y), w3 = __int_as_float(p1.w);
        float w4 = __int_as_float(p2.y), w5 = __int_as_float(p2.w);
        float w6 = __int_as_float(p3.y), w7 = __int_as_float(p3.w);
        acc.x = fmaf(w0, v0.x, acc.x); acc.y = fmaf(w0, v0.y, acc.y);
        acc.x = fmaf(w1, v1.x, acc.x); acc.y = fmaf(w1, v1.y, acc.y);
        acc.x = fmaf(w2, v2.x, acc.x); acc.y = fmaf(w2, v2.y, acc.y);
        acc.x = fmaf(w3, v3.x, acc.x); acc.y = fmaf(w3, v3.y, acc.y);
        acc.x = fmaf(w4, v4.x, acc.x); acc.y = fmaf(w4, v4.y, acc.y);
        acc.x = fmaf(w5, v5.x, acc.x); acc.y = fmaf(w5, v5.y, acc.y);
        acc.x = fmaf(w6, v6.x, acc.x); acc.y = fmaf(w6, v6.y, acc.y);
        acc.x = fmaf(w7, v7.x, acc.x); acc.y = fmaf(w7, v7.y, acc.y);
    }
    for (; j + 1 < end; j += 2) {
        int4 p = csr4[j >> 1];
        float2 v0 = __half22float2(*reinterpret_cast<const __half2*>(&g_S1h[p.x * NHID + 2 * lane]));
        float2 v1 = __half22float2(*reinterpret_cast<const __half2*>(&g_S1h[p.z * NHID + 2 * lane]));
        float w0 = __int_as_float(p.y), w1 = __int_as_float(p.w);
        acc.x = fmaf(w0, v0.x, acc.x); acc.y = fmaf(w0, v0.y, acc.y);
        acc.x = fmaf(w1, v1.x, acc.x); acc.y = fmaf(w1, v1.y, acc.y);
    }
    if (j < end) {
        int2 e = g_csr[j];
        float2 v = __half22float2(*reinterpret_cast<const __half2*>(&g_S1h[e.x * NHID + 2 * lane]));
        float wt = __int_as_float(e.y);
        acc.x = fmaf(wt, v.x, acc.x); acc.y = fmaf(wt, v.y, acc.y);
    }
    *reinterpret_cast<float2*>(&g_H[d * NHID + 2 * lane]) = acc;
}

// ---------------------------------------------------------------------------
// GEMM2 fused ReLU: S2[N,16] = relu(H)[N,64] @ W2[64,16], fp16 output
// ---------------------------------------------------------------------------
__global__ void __launch_bounds__(256) gemm2_kernel(
    const float* __restrict__ W2, int n_nodes)
{
    __shared__ float hs[128][68];
    __shared__ float ws2[64][16];

    const int tid = threadIdx.x;
    const int tx = tid & 3;
    const int ty = tid >> 2;
    const int rowBase = blockIdx.x * 128;

#pragma unroll
    for (int j = 0; j < 8; j++) {
        int s = tid + j * 256;
        int r = s >> 4;
        int c4 = s & 15;
        float4 v = make_float4(0.f, 0.f, 0.f, 0.f);
        int grow = rowBase + r;
        if (grow < n_nodes)
            v = *reinterpret_cast<const float4*>(&g_H[grow * NHID + c4 * 4]);
        v.x = fmaxf(v.x, 0.f); v.y = fmaxf(v.y, 0.f);
        v.z = fmaxf(v.z, 0.f); v.w = fmaxf(v.w, 0.f);
        *reinterpret_cast<float4*>(&hs[r][c4 * 4]) = v;
    }
    {
        int kk = tid >> 2;
        int c4 = tid & 3;
        float4 v = *reinterpret_cast<const float4*>(&W2[kk * NCLASS + c4 * 4]);
        *reinterpret_cast<float4*>(&ws2[kk][c4 * 4]) = v;
    }
    __syncthreads();

    float acc0[4] = {0.f, 0.f, 0.f, 0.f};
    float acc1[4] = {0.f, 0.f, 0.f, 0.f};
#pragma unroll
    for (int kk = 0; kk < NHID; kk++) {
        float a0 = hs[ty][kk];
        float a1 = hs[ty + 64][kk];
        float4 w = *reinterpret_cast<const float4*>(&ws2[kk][4 * tx]);
        acc0[0] = fmaf(a0, w.x, acc0[0]); acc0[1] = fmaf(a0, w.y, acc0[1]);
        acc0[2] = fmaf(a0, w.z, acc0[2]); acc0[3] = fmaf(a0, w.w, acc0[3]);
        acc1[0] = fmaf(a1, w.x, acc1[0]); acc1[1] = fmaf(a1, w.y, acc1[1]);
        acc1[2] = fmaf(a1, w.z, acc1[2]); acc1[3] = fmaf(a1, w.w, acc1[3]);
    }

    int r0 = rowBase + ty, r1 = rowBase + ty + 64;
    if (r0 < n_nodes) {
        __half2 h2[2] = { __floats2half2_rn(acc0[0], acc0[1]),
                          __floats2half2_rn(acc0[2], acc0[3]) };
        *reinterpret_cast<uint2*>(&g_S2h[r0 * NCLASS + 4 * tx]) =
            *reinterpret_cast<const uint2*>(h2);
    }
    if (r1 < n_nodes) {
        __half2 h2[2] = { __floats2half2_rn(acc1[0], acc1[1]),
                          __floats2half2_rn(acc1[2], acc1[3]) };
        *reinterpret_cast<uint2*>(&g_S2h[r1 * NCLASS + 4 * tx]) =
            *reinterpret_cast<const uint2*>(h2);
    }
}

// ---------------------------------------------------------------------------
// SpMM2 (pull) + bias + log_softmax fused: out[d] = lsm(b2 + sum w*S2[src])
// ---------------------------------------------------------------------------
__global__ void __launch_bounds__(256) spmm2_lsm_kernel(
    const float* __restrict__ b2, float* __restrict__ out, int n_nodes)
{
    int lane16 = threadIdx.x & 15;
    int d = blockIdx.x * 16 + (threadIdx.x >> 4);
    if (d >= n_nodes) return;

    float acc = b2[lane16];
    int beg = g_off[d];
    int end = beg + g_cnt[d];
    int j = beg;

    if ((j & 1) && j < end) {
        int2 e = g_csr[j];
        acc = fmaf(__int_as_float(e.y), __half2float(g_S2h[e.x * NCLASS + lane16]), acc);
        j++;
    }
    const int4* csr4 = reinterpret_cast<const int4*>(g_csr);
    for (; j + 3 < end; j += 4) {
        int h = j >> 1;
        int4 p0 = csr4[h], p1 = csr4[h + 1];
        float v0 = __half2float(g_S2h[p0.x * NCLASS + lane16]);
        float v1 = __half2float(g_S2h[p0.z * NCLASS + lane16]);
        float v2 = __half2float(g_S2h[p1.x * NCLASS + lane16]);
        float v3 = __half2float(g_S2h[p1.z * NCLASS + lane16]);
        acc = fmaf(__int_as_float(p0.y), v0, acc);
        acc = fmaf(__int_as_float(p0.w), v1, acc);
        acc = fmaf(__int_as_float(p1.y), v2, acc);
        acc = fmaf(__int_as_float(p1.w), v3, acc);
    }
    for (; j < end; j++) {
        int2 e = g_csr[j];
        acc = fmaf(__int_as_float(e.y), __half2float(g_S2h[e.x * NCLASS + lane16]), acc);
    }

    float m = acc;
#pragma unroll
    for (int o = 8; o >= 1; o >>= 1)
        m = fmaxf(m, __shfl_xor_sync(0xffffffffu, m, o, 16));
    float ssum = expf(acc - m);
#pragma unroll
    for (int o = 8; o >= 1; o >>= 1)
        ssum += __shfl_xor_sync(0xffffffffu, ssum, o, 16);
    out[d * NCLASS + lane16] = acc - m - logf(ssum);
}

// ---------------------------------------------------------------------------
// Launch.  Inputs: x, W1, b1, W2, b2, edge_src, edge_dst, edge_weight
// gemm1 forks onto a side stream, overlapping the CSR build; joins before spmm1.
// ---------------------------------------------------------------------------
extern "C" void kernel_launch(void* const* d_in, const int* in_sizes, int n_in,
                              void* d_out, int out_size)
{
    const float* x    = (const float*)d_in[0];
    const float* W1   = (const float*)d_in[1];
    const float* b1   = (const float*)d_in[2];
    const float* W2   = (const float*)d_in[3];
    const float* b2   = (const float*)d_in[4];
    const int*   esrc = (const int*)d_in[5];
    const int*   edst = (const int*)d_in[6];
    const float* ew   = (const float*)d_in[7];

    int n_nodes = in_sizes[0] / NFEAT;
    int n_edges = in_sizes[5];
    int nb = (n_nodes + 511) / 512;
    int n4e = (n_edges + 3) / 4;      // 4-edge-per-thread grids
    int n4n = (n_nodes + 3) / 4;

    // Fork: gemm1 (independent of edges) runs concurrently with CSR build.
    cudaStream_t s1;
    cudaEvent_t evFork, evJoin;
    cudaStreamCreateWithFlags(&s1, cudaStreamNonBlocking);
    cudaEventCreateWithFlags(&evFork, cudaEventDisableTiming);
    cudaEventCreateWithFlags(&evJoin, cudaEventDisableTiming);

    cudaEventRecord(evFork, 0);
    cudaStreamWaitEvent(s1, evFork, 0);
    gemm1_tf32_kernel<<<(n_nodes + 63) / 64, 256, 0, s1>>>(x, W1, n_nodes);
    cudaEventRecord(evJoin, s1);

    // CSR-by-dst build (default stream)
    zero_cnt_kernel<<<(n4n + 255) / 256, 256>>>(n4n);
    hist_rank_kernel<<<(n4e + 255) / 256, 256>>>(edst, n_edges);
    scan_onepass_kernel<<<nb, 512>>>(n_nodes);
    scatter_kernel<<<(n4e + 255) / 256, 256>>>(esrc, edst, ew, n_edges);

    // Join: spmm1 needs both S1 and the CSR.
    cudaStreamWaitEvent(0, evJoin, 0);

    spmm1_pull_kernel<<<(n_nodes + 7) / 8, 256>>>(b1, n_nodes);
    gemm2_kernel<<<(n_nodes + 127) / 128, 256>>>(W2, n_nodes);
    spmm2_lsm_kernel<<<(n_nodes + 15) / 16, 256>>>(b2, (float*)d_out, n_nodes);

    cudaEventDestroy(evFork);
    cudaEventDestroy(evJoin);
    cudaStreamDestroy(s1);
}